// round 2
// baseline (speedup 1.0000x reference)
#include <cuda_runtime.h>
#include <cstdint>

// out[b,i,j,o] = x[b,2i,2j, o&31] + x[b,2i,2j+1, (o>>5)&15]
//              + x[b,2i+1,2j, 0]  + x[b,2i+1,2j+1, 0]
// (one-hot conv kernel collapses to gather-add; c2=c3=0 since C_OUT=512 < 32^2)

#define B_DIM 64
#define H_DIM 128
#define W_DIM 128
#define C_IN 32
#define OH 64
#define OW 64
#define C_OUT 512
#define NPIX (B_DIM * OH * OW)        // 262144 output pixels
#define PIX_PER_WARP 2
#define NWARPS (NPIX / PIX_PER_WARP)  // 131072 warps

__global__ void __launch_bounds__(256, 8)
conv2dproduct_kernel(const float* __restrict__ x, float* __restrict__ out) {
    const int w    = (blockIdx.x * blockDim.x + threadIdx.x) >> 5;
    const int lane = threadIdx.x & 31;
    if (w >= NWARPS) return;

    const unsigned FULL = 0xFFFFFFFFu;
    const int p0 = w * PIX_PER_WARP;

    // ---- issue all loads up front (MLP = 8 independent LDGs) ----
    const float* px[PIX_PER_WARP];
    float a[PIX_PER_WARP], bvals[PIX_PER_WARP], c0[PIX_PER_WARP], d0[PIX_PER_WARP];
#pragma unroll
    for (int t = 0; t < PIX_PER_WARP; t++) {
        const int p = p0 + t;
        const int j = p & 63;
        const int i = (p >> 6) & 63;
        const int b = p >> 12;
        px[t] = x + ((((size_t)b * H_DIM + 2 * i) * W_DIM) + 2 * j) * C_IN;
    }
#pragma unroll
    for (int t = 0; t < PIX_PER_WARP; t++) {
        a[t]     = __ldg(px[t] + lane);                       // 128B line
        bvals[t] = __ldg(px[t] + C_IN + (lane & 15));         // 64B (2 sectors)
        c0[t]    = __ldg(px[t] + (size_t)W_DIM * C_IN);       // 32B sector
        d0[t]    = __ldg(px[t] + (size_t)W_DIM * C_IN + C_IN);
    }

    // Lane's float4 of `a` comes from lanes 4*(lane&7)..+3 (chunk-invariant).
    const int jj = (lane & 7) * 4;
    float f0[PIX_PER_WARP], f1[PIX_PER_WARP], f2[PIX_PER_WARP], f3[PIX_PER_WARP];
    float base[PIX_PER_WARP];
#pragma unroll
    for (int t = 0; t < PIX_PER_WARP; t++) {
        f0[t] = __shfl_sync(FULL, a[t], jj);
        f1[t] = __shfl_sync(FULL, a[t], jj + 1);
        f2[t] = __shfl_sync(FULL, a[t], jj + 2);
        f3[t] = __shfl_sync(FULL, a[t], jj + 3);
        base[t] = c0[t] + d0[t];
    }

    // ---- 8 streaming STG.128, interleaved across the two pixels ----
#pragma unroll
    for (int chunk = 0; chunk < 4; chunk++) {
        const int g = chunk * 4 + (lane >> 3);  // b-index 0..15
#pragma unroll
        for (int t = 0; t < PIX_PER_WARP; t++) {
            const float s = __shfl_sync(FULL, bvals[t], g) + base[t];
            float4 v;
            v.x = f0[t] + s;
            v.y = f1[t] + s;
            v.z = f2[t] + s;
            v.w = f3[t] + s;
            float4* o4 = reinterpret_cast<float4*>(out + (size_t)(p0 + t) * C_OUT)
                         + chunk * 32 + lane;
            __stcs(o4, v);  // streaming: evict-first, output never re-read
        }
    }
}

extern "C" void kernel_launch(void* const* d_in, const int* in_sizes, int n_in,
                              void* d_out, int out_size) {
    const float* x = (const float*)d_in[0];
    float* out = (float*)d_out;

    const int total_threads = NWARPS * 32;
    const int block = 256;
    const int grid = (total_threads + block - 1) / block;  // 16384
    conv2dproduct_kernel<<<grid, block>>>(x, out);
}